// round 6
// baseline (speedup 1.0000x reference)
#include <cuda_runtime.h>
#include <cstdint>

// RoIAlign (torchvision, aligned=false), POOLED=7, SCALE=1, SR=2.
// features: [2,256,200,200] f32, rois: [512,5] f32, out: [512,256,7,7] f32
//
// R6: merge the (x0, x0+1) corner pair into one aligned LDG.64 per row.
//  - o2 = o & ~1 is always 8B-aligned (WW even -> row parity = x0 parity).
//  - even x0: float2 = {x0, x0+1}; odd x0: float2 = {x0-1, x0} plus a
//    predicated LDG.32 for x0+1 (only odd lanes active -> no extra sectors
//    from even lanes).
//  - x-weights become 3 taps (u0,u1,u2); row weights hy*vs, ly*vs separate.
//  - Everything else as R4/R5: warp = bin-row, lane = pw*4+sample,
//    shfl_xor(1,2) combine, channel unroll x4.

#define CCH    256
#define HH     200
#define WW     200
#define PP     7
#define KROIS  512
#define NBINS  (PP * PP)        // 49
#define NSAMP  (NBINS * 4)      // 196
#define PLANE  (HH * WW)        // 40000
#define CSPLIT 8
#define CCHUNK (CCH / CSPLIT)   // 32
#define TPB    224              // 7 warps

__global__ __launch_bounds__(TPB, 8)
void roi_align_kernel(const float* __restrict__ feat,
                      const float* __restrict__ rois,
                      float* __restrict__ out)
{
    __shared__ int    s_o2[NSAMP];      // [pp*4 + s] aligned base offset
    __shared__ float4 s_u[NSAMP];       // (u0, u1, u2, hy*vs)
    __shared__ float  s_ly[NSAMP];      // ly*vs
    __shared__ int    s_b;

    const int k     = blockIdx.x;
    const int cbase = blockIdx.y * CCHUNK;
    const int tid   = threadIdx.x;

    // --- per-ROI sample table (layout [pp][s]) -------------------------
    const float r0 = rois[k * 5 + 0];
    const float x1 = rois[k * 5 + 1];
    const float y1 = rois[k * 5 + 2];
    const float x2 = rois[k * 5 + 3];
    const float y2 = rois[k * 5 + 4];

    const float roi_w = fmaxf(x2 - x1, 1.0f);
    const float roi_h = fmaxf(y2 - y1, 1.0f);
    const float bin_w = roi_w * (1.0f / PP);
    const float bin_h = roi_h * (1.0f / PP);

    if (tid == 0) s_b = (int)r0;

    if (tid < NSAMP) {
        const int pp = tid >> 2;         // bin 0..48 (ph*7+pw)
        const int s  = tid & 3;          // sample 0..3 (sy*2+sx)
        const int ph = pp / PP;
        const int pw = pp - ph * PP;
        const int sy = s >> 1;
        const int sx = s & 1;

        const float gy = (float)ph + ((float)sy + 0.5f) * 0.5f;
        const float gx = (float)pw + ((float)sx + 0.5f) * 0.5f;
        float y = y1 + gy * bin_h;
        float x = x1 + gx * bin_w;

        const bool valid = (y >= -1.0f) && (y <= (float)HH) &&
                           (x >= -1.0f) && (x <= (float)WW);

        y = fminf(fmaxf(y, 0.0f), (float)(HH - 1));
        x = fminf(fmaxf(x, 0.0f), (float)(WW - 1));

        int y0 = (int)floorf(y); if (y0 > HH - 2) y0 = HH - 2;
        int x0 = (int)floorf(x); if (x0 > WW - 2) x0 = WW - 2;

        const float ly = y - (float)y0;
        const float lx = x - (float)x0;
        const float hy = 1.0f - ly;
        const float hx = 1.0f - lx;
        const float vs = valid ? 0.25f : 0.0f;   // fold mean(1/4) + validity

        const int o   = y0 * WW + x0;
        const bool od = (x0 & 1) != 0;

        s_o2[tid] = o & ~1;
        // 3-tap x weights over {o2, o2+1, o2+2}
        s_u[tid]  = od ? make_float4(0.0f, hx, lx, hy * vs)
                       : make_float4(hx, lx, 0.0f, hy * vs);
        s_ly[tid] = ly * vs;
    }
    __syncthreads();

    const int warp = tid >> 5;           // 0..6 = bin-row ph
    const int lane = tid & 31;
    const int pw   = lane >> 2;          // 0..7 (7 valid)
    const bool act = (lane < 28);
    const int pp   = warp * PP + (act ? pw : 6);
    const int si   = pp * 4 + (lane & 3);

    const int    o2  = s_o2[si];
    const float4 u   = s_u[si];
    const float  lyv = s_ly[si];
    const bool   ext = act && (u.z != 0.0f);   // need the x0+1 tap?

    const float* __restrict__ fbase = feat + (size_t)s_b * (CCH * PLANE)
                                           + (size_t)cbase * PLANE + o2;
    float* __restrict__        ob   = out  + (size_t)k * (CCH * NBINS)
                                           + (size_t)cbase * NBINS;

    const bool wr = act && ((lane & 3) == 0);

    #pragma unroll 1
    for (int c = 0; c < CCHUNK; c += 4) {
        const float* p = fbase + (size_t)c * PLANE;

        float2 f0 = make_float2(0.f, 0.f), g0 = f0;
        float2 f1 = f0, g1 = f0, f2v = f0, g2v = f0, f3 = f0, g3 = f0;
        float  e0t = 0.f, e0b = 0.f, e1t = 0.f, e1b = 0.f;
        float  e2t = 0.f, e2b = 0.f, e3t = 0.f, e3b = 0.f;

        if (act) {
            f0  = *(const float2*)(p);
            g0  = *(const float2*)(p + WW);
            f1  = *(const float2*)(p + PLANE);
            g1  = *(const float2*)(p + PLANE + WW);
            f2v = *(const float2*)(p + 2 * PLANE);
            g2v = *(const float2*)(p + 2 * PLANE + WW);
            f3  = *(const float2*)(p + 3 * PLANE);
            g3  = *(const float2*)(p + 3 * PLANE + WW);
        }
        if (ext) {
            e0t = p[2];              e0b = p[WW + 2];
            e1t = p[PLANE + 2];      e1b = p[PLANE + WW + 2];
            e2t = p[2 * PLANE + 2];  e2b = p[2 * PLANE + WW + 2];
            e3t = p[3 * PLANE + 2];  e3b = p[3 * PLANE + WW + 2];
        }

        float v0 = u.w * (u.x * f0.x  + u.y * f0.y  + u.z * e0t)
                 + lyv * (u.x * g0.x  + u.y * g0.y  + u.z * e0b);
        float v1 = u.w * (u.x * f1.x  + u.y * f1.y  + u.z * e1t)
                 + lyv * (u.x * g1.x  + u.y * g1.y  + u.z * e1b);
        float v2 = u.w * (u.x * f2v.x + u.y * f2v.y + u.z * e2t)
                 + lyv * (u.x * g2v.x + u.y * g2v.y + u.z * e2b);
        float v3 = u.w * (u.x * f3.x  + u.y * f3.y  + u.z * e3t)
                 + lyv * (u.x * g3.x  + u.y * g3.y  + u.z * e3b);

        v0 += __shfl_xor_sync(0xFFFFFFFFu, v0, 1);
        v1 += __shfl_xor_sync(0xFFFFFFFFu, v1, 1);
        v2 += __shfl_xor_sync(0xFFFFFFFFu, v2, 1);
        v3 += __shfl_xor_sync(0xFFFFFFFFu, v3, 1);
        v0 += __shfl_xor_sync(0xFFFFFFFFu, v0, 2);
        v1 += __shfl_xor_sync(0xFFFFFFFFu, v1, 2);
        v2 += __shfl_xor_sync(0xFFFFFFFFu, v2, 2);
        v3 += __shfl_xor_sync(0xFFFFFFFFu, v3, 2);

        if (wr) {
            ob[(size_t)(c + 0) * NBINS + pp] = v0;
            ob[(size_t)(c + 1) * NBINS + pp] = v1;
            ob[(size_t)(c + 2) * NBINS + pp] = v2;
            ob[(size_t)(c + 3) * NBINS + pp] = v3;
        }
    }
}

extern "C" void kernel_launch(void* const* d_in, const int* in_sizes, int n_in,
                              void* d_out, int out_size)
{
    const float* feat = (const float*)d_in[0];
    const float* rois = (const float*)d_in[1];
    float*       out  = (float*)d_out;

    dim3 grid(KROIS, CSPLIT);
    roi_align_kernel<<<grid, TPB>>>(feat, rois, out);
}

// round 7
// speedup vs baseline: 1.1876x; 1.1876x over previous
#include <cuda_runtime.h>
#include <cstdint>

// RoIAlign (torchvision, aligned=false), POOLED=7, SCALE=1, SR=2.
// features: [2,256,200,200] f32, rois: [512,5] f32, out: [512,256,7,7] f32
//
// R7: revert to R5 gather structure (R6's LDG.64+ext regressed);
// channel unroll x8 -> 32 independent LDG.32 in flight per lane.
// Loads unpredicated: idle lanes 28-31 duplicate bin-6 addresses (same
// sectors as lanes 24-27 -> free), removing the predicate chain.

#define CCH    256
#define HH     200
#define WW     200
#define PP     7
#define KROIS  512
#define NBINS  (PP * PP)        // 49
#define NSAMP  (NBINS * 4)      // 196
#define PLANE  (HH * WW)        // 40000
#define CSPLIT 8
#define CCHUNK (CCH / CSPLIT)   // 32
#define TPB    224              // 7 warps
#define UNR    8

__global__ __launch_bounds__(TPB)
void roi_align_kernel(const float* __restrict__ feat,
                      const float* __restrict__ rois,
                      float* __restrict__ out)
{
    __shared__ int    s_off[NSAMP];     // [pp*4 + s]
    __shared__ float4 s_w[NSAMP];       // [pp*4 + s]
    __shared__ int    s_b;

    const int k     = blockIdx.x;
    const int cbase = blockIdx.y * CCHUNK;
    const int tid   = threadIdx.x;

    // --- per-ROI sample table (layout [pp][s]) -------------------------
    const float r0 = rois[k * 5 + 0];
    const float x1 = rois[k * 5 + 1];
    const float y1 = rois[k * 5 + 2];
    const float x2 = rois[k * 5 + 3];
    const float y2 = rois[k * 5 + 4];

    const float roi_w = fmaxf(x2 - x1, 1.0f);
    const float roi_h = fmaxf(y2 - y1, 1.0f);
    const float bin_w = roi_w * (1.0f / PP);
    const float bin_h = roi_h * (1.0f / PP);

    if (tid == 0) s_b = (int)r0;

    if (tid < NSAMP) {
        const int pp = tid >> 2;         // bin 0..48 (ph*7+pw)
        const int s  = tid & 3;          // sample 0..3 (sy*2+sx)
        const int ph = pp / PP;
        const int pw = pp - ph * PP;
        const int sy = s >> 1;
        const int sx = s & 1;

        const float gy = (float)ph + ((float)sy + 0.5f) * 0.5f;
        const float gx = (float)pw + ((float)sx + 0.5f) * 0.5f;
        float y = y1 + gy * bin_h;
        float x = x1 + gx * bin_w;

        const bool valid = (y >= -1.0f) && (y <= (float)HH) &&
                           (x >= -1.0f) && (x <= (float)WW);

        y = fminf(fmaxf(y, 0.0f), (float)(HH - 1));
        x = fminf(fmaxf(x, 0.0f), (float)(WW - 1));

        int y0 = (int)floorf(y); if (y0 > HH - 2) y0 = HH - 2;
        int x0 = (int)floorf(x); if (x0 > WW - 2) x0 = WW - 2;

        const float ly = y - (float)y0;
        const float lx = x - (float)x0;
        const float hy = 1.0f - ly;
        const float hx = 1.0f - lx;
        const float vs = valid ? 0.25f : 0.0f;   // fold mean(1/4) + validity

        s_off[tid] = y0 * WW + x0;
        s_w[tid]   = make_float4(hy * hx * vs, hy * lx * vs,
                                 ly * hx * vs, ly * lx * vs);
    }
    __syncthreads();

    const int warp = tid >> 5;           // 0..6 = bin-row ph
    const int lane = tid & 31;
    const int pw   = lane >> 5 ? 6 : (lane >> 2);   // (lane>=28 handled below)
    const bool act = (lane < 28);
    const int pp   = warp * PP + (act ? (lane >> 2) : 6);
    const int si   = pp * 4 + (lane & 3);

    const int    o = s_off[si];
    const float4 w = s_w[si];
    (void)pw;

    const float* __restrict__ fbase = feat + (size_t)s_b * (CCH * PLANE)
                                           + (size_t)cbase * PLANE + o;
    float* __restrict__        ob   = out  + (size_t)k * (CCH * NBINS)
                                           + (size_t)cbase * NBINS;

    const bool wr = act && ((lane & 3) == 0);

    #pragma unroll 1
    for (int c = 0; c < CCHUNK; c += UNR) {
        const float* p = fbase + (size_t)c * PLANE;

        // 32 independent, unpredicated gathers (idle lanes dup bin 6).
        float a[UNR], b[UNR], cc[UNR], d[UNR];
        #pragma unroll
        for (int j = 0; j < UNR; ++j) {
            a[j]  = p[j * PLANE];
            b[j]  = p[j * PLANE + 1];
            cc[j] = p[j * PLANE + WW];
            d[j]  = p[j * PLANE + WW + 1];
        }

        float v[UNR];
        #pragma unroll
        for (int j = 0; j < UNR; ++j)
            v[j] = w.x * a[j] + w.y * b[j] + w.z * cc[j] + w.w * d[j];

        #pragma unroll
        for (int j = 0; j < UNR; ++j)
            v[j] += __shfl_xor_sync(0xFFFFFFFFu, v[j], 1);
        #pragma unroll
        for (int j = 0; j < UNR; ++j)
            v[j] += __shfl_xor_sync(0xFFFFFFFFu, v[j], 2);

        if (wr) {
            #pragma unroll
            for (int j = 0; j < UNR; ++j)
                ob[(size_t)(c + j) * NBINS + pp] = v[j];
        }
    }
}

extern "C" void kernel_launch(void* const* d_in, const int* in_sizes, int n_in,
                              void* d_out, int out_size)
{
    const float* feat = (const float*)d_in[0];
    const float* rois = (const float*)d_in[1];
    float*       out  = (float*)d_out;

    dim3 grid(KROIS, CSPLIT);
    roi_align_kernel<<<grid, TPB>>>(feat, rois, out);
}

// round 8
// speedup vs baseline: 1.1996x; 1.0101x over previous
#include <cuda_runtime.h>
#include <cstdint>

// RoIAlign (torchvision, aligned=false), POOLED=7, SCALE=1, SR=2.
// features: [2,256,200,200] f32, rois: [512,5] f32, out: [512,256,7,7] f32
//
// R8: R4 core (warp = bin-row, lane = pw*4+sample, shfl_xor(1,2) combine,
// channel unroll x4 = 16 LDG in flight) with:
//  - CSPLIT=16 -> 8192 blocks of 16 channels: 6.15 waves instead of 3.07
//    (tail-wave idle ~7% -> ~2.4%).
//  - Unpredicated gathers: idle lanes 28-31 mirror bin-6 addresses (same
//    sectors, free) -> no ISETP/SEL in the hot loop.

#define CCH    256
#define HH     200
#define WW     200
#define PP     7
#define KROIS  512
#define NBINS  (PP * PP)        // 49
#define NSAMP  (NBINS * 4)      // 196
#define PLANE  (HH * WW)        // 40000
#define CSPLIT 16
#define CCHUNK (CCH / CSPLIT)   // 16
#define TPB    224              // 7 warps
#define UNR    4

__global__ __launch_bounds__(TPB, 9)
void roi_align_kernel(const float* __restrict__ feat,
                      const float* __restrict__ rois,
                      float* __restrict__ out)
{
    __shared__ int    s_off[NSAMP];     // [pp*4 + s]
    __shared__ float4 s_w[NSAMP];       // [pp*4 + s]
    __shared__ int    s_b;

    const int k     = blockIdx.x;
    const int cbase = blockIdx.y * CCHUNK;
    const int tid   = threadIdx.x;

    // --- per-ROI sample table (layout [pp][s]) -------------------------
    const float r0 = rois[k * 5 + 0];
    const float x1 = rois[k * 5 + 1];
    const float y1 = rois[k * 5 + 2];
    const float x2 = rois[k * 5 + 3];
    const float y2 = rois[k * 5 + 4];

    const float roi_w = fmaxf(x2 - x1, 1.0f);
    const float roi_h = fmaxf(y2 - y1, 1.0f);
    const float bin_w = roi_w * (1.0f / PP);
    const float bin_h = roi_h * (1.0f / PP);

    if (tid == 0) s_b = (int)r0;

    if (tid < NSAMP) {
        const int pp = tid >> 2;         // bin 0..48 (ph*7+pw)
        const int s  = tid & 3;          // sample 0..3 (sy*2+sx)
        const int ph = pp / PP;
        const int pw = pp - ph * PP;
        const int sy = s >> 1;
        const int sx = s & 1;

        const float gy = (float)ph + ((float)sy + 0.5f) * 0.5f;
        const float gx = (float)pw + ((float)sx + 0.5f) * 0.5f;
        float y = y1 + gy * bin_h;
        float x = x1 + gx * bin_w;

        const bool valid = (y >= -1.0f) && (y <= (float)HH) &&
                           (x >= -1.0f) && (x <= (float)WW);

        y = fminf(fmaxf(y, 0.0f), (float)(HH - 1));
        x = fminf(fmaxf(x, 0.0f), (float)(WW - 1));

        int y0 = (int)floorf(y); if (y0 > HH - 2) y0 = HH - 2;
        int x0 = (int)floorf(x); if (x0 > WW - 2) x0 = WW - 2;

        const float ly = y - (float)y0;
        const float lx = x - (float)x0;
        const float hy = 1.0f - ly;
        const float hx = 1.0f - lx;
        const float vs = valid ? 0.25f : 0.0f;   // fold mean(1/4) + validity

        s_off[tid] = y0 * WW + x0;
        s_w[tid]   = make_float4(hy * hx * vs, hy * lx * vs,
                                 ly * hx * vs, ly * lx * vs);
    }
    __syncthreads();

    const int warp = tid >> 5;           // 0..6 = bin-row ph
    const int lane = tid & 31;
    const bool act = (lane < 28);
    const int pp   = warp * PP + (act ? (lane >> 2) : 6);
    const int si   = pp * 4 + (lane & 3);

    const int    o = s_off[si];
    const float4 w = s_w[si];

    const float* __restrict__ fbase = feat + (size_t)s_b * (CCH * PLANE)
                                           + (size_t)cbase * PLANE + o;
    float* __restrict__        ob   = out  + (size_t)k * (CCH * NBINS)
                                           + (size_t)cbase * NBINS + pp;

    const bool wr = act && ((lane & 3) == 0);

    #pragma unroll 1
    for (int c = 0; c < CCHUNK; c += UNR) {
        const float* p = fbase + (size_t)c * PLANE;

        // 16 independent, unpredicated gathers (idle lanes dup bin 6 -> free).
        float a[UNR], b[UNR], cc[UNR], d[UNR];
        #pragma unroll
        for (int j = 0; j < UNR; ++j) {
            a[j]  = p[j * PLANE];
            b[j]  = p[j * PLANE + 1];
            cc[j] = p[j * PLANE + WW];
            d[j]  = p[j * PLANE + WW + 1];
        }

        float v[UNR];
        #pragma unroll
        for (int j = 0; j < UNR; ++j)
            v[j] = w.x * a[j] + w.y * b[j] + w.z * cc[j] + w.w * d[j];

        #pragma unroll
        for (int j = 0; j < UNR; ++j)
            v[j] += __shfl_xor_sync(0xFFFFFFFFu, v[j], 1);
        #pragma unroll
        for (int j = 0; j < UNR; ++j)
            v[j] += __shfl_xor_sync(0xFFFFFFFFu, v[j], 2);

        if (wr) {
            #pragma unroll
            for (int j = 0; j < UNR; ++j)
                ob[(size_t)(c + j) * NBINS] = v[j];
        }
    }
}

extern "C" void kernel_launch(void* const* d_in, const int* in_sizes, int n_in,
                              void* d_out, int out_size)
{
    const float* feat = (const float*)d_in[0];
    const float* rois = (const float*)d_in[1];
    float*       out  = (float*)d_out;

    dim3 grid(KROIS, CSPLIT);
    roi_align_kernel<<<grid, TPB>>>(feat, rois, out);
}